// round 1
// baseline (speedup 1.0000x reference)
#include <cuda_runtime.h>
#include <math.h>

#define NB    2
#define LSEQ  2048
#define HEADS 16
#define HD    64
#define EMB   1024

// scratch (static device arrays: allocation-free)
__device__ float    g_qp[NB*HEADS*LSEQ*HD];
__device__ float    g_kp[NB*HEADS*LSEQ*HD];
__device__ float    g_vp[NB*HEADS*LSEQ*HD];
__device__ float    g_att[NB*LSEQ*EMB];
__device__ unsigned g_mb[NB*LSEQ*(LSEQ/32)];

// XOR swizzle on the column index of a [64][64] smem tile: kills bank
// conflicts on transposed stores while keeping float4 reads aligned+conflict-free.
__device__ __forceinline__ int swz(int e, int c) {
    return c ^ (((e >> 2) & 7) << 2);
}

// ---------------------------------------------------------------------------
// Kernel 1: per-head projections q' = q@Wq^T, k' = k@Wk^T, v' = v@Wv^T
// out layout: [n][h][l][d] (head-major, contiguous d) for the attention kernel.
// ---------------------------------------------------------------------------
__global__ __launch_bounds__(256) void proj_kernel(
    const float* __restrict__ vals, const float* __restrict__ keys,
    const float* __restrict__ quer, const float* __restrict__ Wv,
    const float* __restrict__ Wk,   const float* __restrict__ Wq)
{
    __shared__ float At[64*64];   // [e][row] swizzled
    __shared__ float Bt[64*64];   // [e][col] swizzled
    const int l0  = blockIdx.x * 64;
    const int h   = blockIdx.y;
    const int n   = blockIdx.z;
    const int tid = threadIdx.x;
    const int tx  = tid & 15, ty = tid >> 4;
    const int row = ty;
    const int e4  = tx * 4;

    const float* xsrc[3] = {quer, keys, vals};
    const float* wsrc[3] = {Wq, Wk, Wv};
    float* dst[3];
    dst[0] = g_qp; dst[1] = g_kp; dst[2] = g_vp;

    for (int t = 0; t < 3; ++t) {
        __syncthreads();
        const float* x = xsrc[t];
        const float* w = wsrc[t];
        #pragma unroll
        for (int rr = 0; rr < 64; rr += 16) {
            int r = rr + row;
            float4 xv = *(const float4*)(x + (size_t)(n*LSEQ + l0 + r)*EMB + h*HD + e4);
            At[(e4+0)*64 + swz(e4+0, r)] = xv.x;
            At[(e4+1)*64 + swz(e4+1, r)] = xv.y;
            At[(e4+2)*64 + swz(e4+2, r)] = xv.z;
            At[(e4+3)*64 + swz(e4+3, r)] = xv.w;
            float4 wv = *(const float4*)(w + r*HD + e4);
            Bt[(e4+0)*64 + swz(e4+0, r)] = wv.x;
            Bt[(e4+1)*64 + swz(e4+1, r)] = wv.y;
            Bt[(e4+2)*64 + swz(e4+2, r)] = wv.z;
            Bt[(e4+3)*64 + swz(e4+3, r)] = wv.w;
        }
        __syncthreads();
        float c[4][4] = {};
        #pragma unroll 8
        for (int e = 0; e < 64; ++e) {
            float4 a4 = *(const float4*)&At[e*64 + swz(e, ty*4)];
            float4 b4 = *(const float4*)&Bt[e*64 + swz(e, tx*4)];
            float a[4] = {a4.x, a4.y, a4.z, a4.w};
            float b[4] = {b4.x, b4.y, b4.z, b4.w};
            #pragma unroll
            for (int i = 0; i < 4; ++i)
                #pragma unroll
                for (int j = 0; j < 4; ++j)
                    c[i][j] = fmaf(a[i], b[j], c[i][j]);
        }
        float* o = dst[t] + ((size_t)(n*HEADS + h)*LSEQ + l0)*HD;
        #pragma unroll
        for (int i = 0; i < 4; ++i) {
            float4 ov = make_float4(c[i][0], c[i][1], c[i][2], c[i][3]);
            *(float4*)(o + (ty*4+i)*HD + tx*4) = ov;
        }
    }
}

// ---------------------------------------------------------------------------
// Kernel 2: pack mask[n][0][q][k] (int 0/1) into bits: g_mb[(n*L+q)*64 + k/32]
// ---------------------------------------------------------------------------
__global__ __launch_bounds__(256) void maskpack_kernel(const int* __restrict__ mask)
{
    const int row  = blockIdx.x;           // n*LSEQ + q
    const int tid  = threadIdx.x;
    const int warp = tid >> 5, lane = tid & 31;
    const int* mrow = mask + (size_t)row * LSEQ;
    #pragma unroll
    for (int it = 0; it < 8; ++it) {
        int k = it*256 + warp*32 + lane;
        unsigned b = __ballot_sync(0xffffffffu, mrow[k] != 0);
        if (lane == 0) g_mb[(size_t)row*64 + it*8 + warp] = b;
    }
}

// ---------------------------------------------------------------------------
// Kernel 3: flash-style masked attention per (n, h, 64-row q tile).
// 48KB static smem: Qt (transposed swizzled), Vs (natural), KP (K transposed
// swizzled, later aliased as P transposed swizzled). 4x4 register tile/thread.
// ---------------------------------------------------------------------------
__global__ __launch_bounds__(256) void attn_kernel()
{
    __shared__ float sm[3*64*64];
    float* Qt = sm;            // [e][r] swizzled
    float* Vs = sm + 4096;     // [c][d] natural
    float* KP = sm + 8192;     // Kt [e][c] swizzled; reused as Pt [c][r] swizzled

    const int q0  = blockIdx.x * 64;
    const int h   = blockIdx.y;
    const int n   = blockIdx.z;
    const int tid = threadIdx.x;
    const int tx  = tid & 15, ty = tid >> 4;
    const int row = ty;
    const int e4  = tx * 4;

    const size_t base = (size_t)(n*HEADS + h) * (LSEQ*HD);
    const float* Q = g_qp + base;
    const float* K = g_kp + base;
    const float* V = g_vp + base;

    // load Q tile transposed+swizzled (once)
    #pragma unroll
    for (int rr = 0; rr < 64; rr += 16) {
        int r = rr + row;
        float4 qv = *(const float4*)(Q + (size_t)(q0 + r)*HD + e4);
        Qt[(e4+0)*64 + swz(e4+0, r)] = qv.x;
        Qt[(e4+1)*64 + swz(e4+1, r)] = qv.y;
        Qt[(e4+2)*64 + swz(e4+2, r)] = qv.z;
        Qt[(e4+3)*64 + swz(e4+3, r)] = qv.w;
    }

    float m[4], l[4], O[4][4];
    #pragma unroll
    for (int i = 0; i < 4; ++i) {
        m[i] = -INFINITY; l[i] = 0.f;
        #pragma unroll
        for (int j = 0; j < 4; ++j) O[i][j] = 0.f;
    }

    const unsigned* mb = g_mb + (size_t)(n*LSEQ + q0) * 64;

    for (int kt = 0; kt < 32; ++kt) {
        __syncthreads();    // prev iteration's PV reads done; Qt visible (iter 0)
        #pragma unroll
        for (int rr = 0; rr < 64; rr += 16) {
            int r = rr + row;
            float4 kv = *(const float4*)(K + (size_t)(kt*64 + r)*HD + e4);
            KP[(e4+0)*64 + swz(e4+0, r)] = kv.x;
            KP[(e4+1)*64 + swz(e4+1, r)] = kv.y;
            KP[(e4+2)*64 + swz(e4+2, r)] = kv.z;
            KP[(e4+3)*64 + swz(e4+3, r)] = kv.w;
            *(float4*)&Vs[r*64 + e4] = *(const float4*)(V + (size_t)(kt*64 + r)*HD + e4);
        }
        __syncthreads();

        // S = Q K^T (rows = q, cols = keys of this tile)
        float s[4][4];
        #pragma unroll
        for (int i = 0; i < 4; ++i)
            #pragma unroll
            for (int j = 0; j < 4; ++j) s[i][j] = 0.f;
        #pragma unroll 8
        for (int e = 0; e < 64; ++e) {
            float4 a4 = *(const float4*)&Qt[e*64 + swz(e, ty*4)];
            float4 b4 = *(const float4*)&KP[e*64 + swz(e, tx*4)];
            float a[4] = {a4.x, a4.y, a4.z, a4.w};
            #pragma unroll
            for (int i = 0; i < 4; ++i) {
                s[i][0] = fmaf(a[i], b4.x, s[i][0]);
                s[i][1] = fmaf(a[i], b4.y, s[i][1]);
                s[i][2] = fmaf(a[i], b4.z, s[i][2]);
                s[i][3] = fmaf(a[i], b4.w, s[i][3]);
            }
        }

        // scale + mask + online softmax (row groups of 16 lanes share a row set)
        const int wofs = kt*2 + (tx >> 3);
        #pragma unroll
        for (int i = 0; i < 4; ++i) {
            unsigned bits = mb[(ty*4 + i)*64 + wofs];
            float mt = -INFINITY;
            #pragma unroll
            for (int j = 0; j < 4; ++j) {
                float sv = s[i][j] * 0.125f;
                if (!((bits >> ((tx*4 + j) & 31)) & 1u)) sv = -1e20f;
                s[i][j] = sv;
                mt = fmaxf(mt, sv);
            }
            #pragma unroll
            for (int off = 8; off > 0; off >>= 1)
                mt = fmaxf(mt, __shfl_xor_sync(0xffffffffu, mt, off));
            float mn   = fmaxf(m[i], mt);
            float corr = __expf(m[i] - mn);
            m[i] = mn;
            float rs = 0.f;
            #pragma unroll
            for (int j = 0; j < 4; ++j) {
                float p = __expf(s[i][j] - mn);
                s[i][j] = p;
                rs += p;
            }
            #pragma unroll
            for (int off = 8; off > 0; off >>= 1)
                rs += __shfl_xor_sync(0xffffffffu, rs, off);
            l[i] = l[i] * corr + rs;
            #pragma unroll
            for (int j = 0; j < 4; ++j) O[i][j] *= corr;
        }

        __syncthreads();    // all K-tile reads done; safe to alias KP as P
        // store P transposed+swizzled: Pt[c][r]
        #pragma unroll
        for (int j = 0; j < 4; ++j) {
            int c = tx*4 + j;
            float4 pv = make_float4(s[0][j], s[1][j], s[2][j], s[3][j]);
            *(float4*)&KP[c*64 + swz(c, ty*4)] = pv;
        }
        __syncthreads();

        // O += P @ V
        #pragma unroll 8
        for (int cc = 0; cc < 64; ++cc) {
            float4 p4 = *(const float4*)&KP[cc*64 + swz(cc, ty*4)];
            float4 v4 = *(const float4*)&Vs[cc*64 + tx*4];
            float p[4] = {p4.x, p4.y, p4.z, p4.w};
            #pragma unroll
            for (int i = 0; i < 4; ++i) {
                O[i][0] = fmaf(p[i], v4.x, O[i][0]);
                O[i][1] = fmaf(p[i], v4.y, O[i][1]);
                O[i][2] = fmaf(p[i], v4.z, O[i][2]);
                O[i][3] = fmaf(p[i], v4.w, O[i][3]);
            }
        }
    }

    // normalize + write to [n][l][h*64+d]
    #pragma unroll
    for (int i = 0; i < 4; ++i) {
        float inv = 1.f / l[i];
        float4 ov = make_float4(O[i][0]*inv, O[i][1]*inv, O[i][2]*inv, O[i][3]*inv);
        *(float4*)(g_att + (size_t)(n*LSEQ + q0 + ty*4 + i)*EMB + h*HD + tx*4) = ov;
    }
}

// ---------------------------------------------------------------------------
// Kernel 4: out = att @ Wo^T + bo   (4096x1024 @ 1024x1024 NT GEMM)
// ---------------------------------------------------------------------------
__global__ __launch_bounds__(256) void outproj_kernel(
    const float* __restrict__ Wo, const float* __restrict__ bo,
    float* __restrict__ out)
{
    __shared__ float At[64*64];   // [i][row] swizzled
    __shared__ float Bt[64*64];   // [i][ocol] swizzled
    const int o0  = blockIdx.x * 64;
    const int r0  = blockIdx.y * 64;
    const int tid = threadIdx.x;
    const int tx  = tid & 15, ty = tid >> 4;
    const int row = ty;
    const int e4  = tx * 4;

    float c[4][4];
    #pragma unroll
    for (int i = 0; i < 4; ++i)
        #pragma unroll
        for (int j = 0; j < 4; ++j) c[i][j] = 0.f;

    for (int ktile = 0; ktile < 16; ++ktile) {
        __syncthreads();
        #pragma unroll
        for (int rr = 0; rr < 64; rr += 16) {
            int r = rr + row;
            float4 av = *(const float4*)(g_att + (size_t)(r0 + r)*EMB + ktile*64 + e4);
            At[(e4+0)*64 + swz(e4+0, r)] = av.x;
            At[(e4+1)*64 + swz(e4+1, r)] = av.y;
            At[(e4+2)*64 + swz(e4+2, r)] = av.z;
            At[(e4+3)*64 + swz(e4+3, r)] = av.w;
            float4 wv = *(const float4*)(Wo + (size_t)(o0 + r)*EMB + ktile*64 + e4);
            Bt[(e4+0)*64 + swz(e4+0, r)] = wv.x;
            Bt[(e4+1)*64 + swz(e4+1, r)] = wv.y;
            Bt[(e4+2)*64 + swz(e4+2, r)] = wv.z;
            Bt[(e4+3)*64 + swz(e4+3, r)] = wv.w;
        }
        __syncthreads();
        #pragma unroll 8
        for (int e = 0; e < 64; ++e) {
            float4 a4 = *(const float4*)&At[e*64 + swz(e, ty*4)];
            float4 b4 = *(const float4*)&Bt[e*64 + swz(e, tx*4)];
            float a[4] = {a4.x, a4.y, a4.z, a4.w};
            #pragma unroll
            for (int i = 0; i < 4; ++i) {
                c[i][0] = fmaf(a[i], b4.x, c[i][0]);
                c[i][1] = fmaf(a[i], b4.y, c[i][1]);
                c[i][2] = fmaf(a[i], b4.z, c[i][2]);
                c[i][3] = fmaf(a[i], b4.w, c[i][3]);
            }
        }
    }

    float4 bv = *(const float4*)(bo + o0 + tx*4);
    #pragma unroll
    for (int i = 0; i < 4; ++i) {
        float4 ov = make_float4(c[i][0]+bv.x, c[i][1]+bv.y, c[i][2]+bv.z, c[i][3]+bv.w);
        *(float4*)(out + (size_t)(r0 + ty*4 + i)*EMB + o0 + tx*4) = ov;
    }
}

// ---------------------------------------------------------------------------
extern "C" void kernel_launch(void* const* d_in, const int* in_sizes, int n_in,
                              void* d_out, int out_size)
{
    (void)in_sizes; (void)n_in; (void)out_size;
    const float* vals = (const float*)d_in[0];
    const float* keys = (const float*)d_in[1];
    const float* quer = (const float*)d_in[2];
    const int*   mask = (const int*)  d_in[3];
    const float* Wv   = (const float*)d_in[4];
    const float* Wk   = (const float*)d_in[5];
    const float* Wq   = (const float*)d_in[6];
    const float* Wo   = (const float*)d_in[7];
    const float* bo   = (const float*)d_in[8];
    float* out = (float*)d_out;

    proj_kernel   <<<dim3(LSEQ/64, HEADS, NB), 256>>>(vals, keys, quer, Wv, Wk, Wq);
    maskpack_kernel<<<NB*LSEQ, 256>>>(mask);
    attn_kernel   <<<dim3(LSEQ/64, HEADS, NB), 256>>>();
    outproj_kernel<<<dim3(EMB/64, NB*LSEQ/64), 256>>>(Wo, bo, out);
}

// round 6
// speedup vs baseline: 2.1862x; 2.1862x over previous
#include <cuda_runtime.h>
#include <math.h>
#include <stdint.h>

#define NB    2
#define LSEQ  2048
#define HEADS 16
#define HD    64
#define EMB   1024

// scratch (static device arrays: allocation-free)
__device__ float    g_qp[NB*HEADS*LSEQ*HD];
__device__ float    g_kp[NB*HEADS*LSEQ*HD];
__device__ float    g_vp[NB*HEADS*LSEQ*HD];
__device__ float    g_att[NB*LSEQ*EMB];
__device__ float    g_wo[EMB*EMB];
__device__ unsigned g_mb[NB*LSEQ*(LSEQ/32)];

// ---------------------------------------------------------------------------
// helpers
// ---------------------------------------------------------------------------
// round-to-nearest tf32; PTX requires .b32 destination for cvt.*.tf32.f32
__device__ __forceinline__ uint32_t tf32bits(float x) {
    uint32_t r;
    asm("cvt.rna.tf32.f32 %0, %1;" : "=r"(r) : "f"(x));
    return r;
}
__device__ __forceinline__ float tf32r(float x) {
    return __uint_as_float(tf32bits(x));
}
__device__ __forceinline__ uint32_t smem_u32(const void* p) {
    uint32_t a;
    asm("{ .reg .u64 t; cvta.to.shared.u64 t, %1; cvt.u32.u64 %0, t; }" : "=r"(a) : "l"(p));
    return a;
}
__device__ __forceinline__ void cpasync16(uint32_t dst, const void* src) {
    asm volatile("cp.async.cg.shared.global [%0], [%1], 16;" :: "r"(dst), "l"(src));
}
#define CP_COMMIT() asm volatile("cp.async.commit_group;" ::: "memory")
#define CP_WAIT1()  asm volatile("cp.async.wait_group 1;" ::: "memory")

// m16n8k8 tf32 tensor-core mma (baseline PTX, works on plain sm_100 target)
__device__ __forceinline__ void mma8(float c[4], const uint32_t a[4],
                                     uint32_t b0, uint32_t b1) {
    asm volatile(
        "mma.sync.aligned.m16n8k8.row.col.f32.tf32.tf32.f32 "
        "{%0,%1,%2,%3}, {%4,%5,%6,%7}, {%8,%9}, {%0,%1,%2,%3};"
        : "+f"(c[0]), "+f"(c[1]), "+f"(c[2]), "+f"(c[3])
        : "r"(a[0]), "r"(a[1]), "r"(a[2]), "r"(a[3]), "r"(b0), "r"(b1));
}

// fp32 CUDA-core smem swizzle (proj kernel)
__device__ __forceinline__ int swz(int e, int c) { return c ^ (((e >> 2) & 7) << 2); }

// ---------------------------------------------------------------------------
// Kernel 1: per-head projections (fp32 compute, tf32-rounded OUTPUT so the
// attention kernel can cp.async the data raw).
// ---------------------------------------------------------------------------
__global__ __launch_bounds__(256) void proj_kernel(
    const float* __restrict__ vals, const float* __restrict__ keys,
    const float* __restrict__ quer, const float* __restrict__ Wv,
    const float* __restrict__ Wk,   const float* __restrict__ Wq)
{
    __shared__ float At[64*64];
    __shared__ float Bt[64*64];
    const int l0  = blockIdx.x * 64;
    const int h   = blockIdx.y;
    const int n   = blockIdx.z;
    const int tid = threadIdx.x;
    const int tx  = tid & 15, ty = tid >> 4;
    const int e4  = tx * 4;

    const float* xsrc[3] = {quer, keys, vals};
    const float* wsrc[3] = {Wq, Wk, Wv};
    float* dst[3];
    dst[0] = g_qp; dst[1] = g_kp; dst[2] = g_vp;

    for (int t = 0; t < 3; ++t) {
        __syncthreads();
        const float* x = xsrc[t];
        const float* w = wsrc[t];
        #pragma unroll
        for (int rr = 0; rr < 64; rr += 16) {
            int r = rr + ty;
            float4 xv = *(const float4*)(x + (size_t)(n*LSEQ + l0 + r)*EMB + h*HD + e4);
            At[(e4+0)*64 + swz(e4+0, r)] = xv.x;
            At[(e4+1)*64 + swz(e4+1, r)] = xv.y;
            At[(e4+2)*64 + swz(e4+2, r)] = xv.z;
            At[(e4+3)*64 + swz(e4+3, r)] = xv.w;
            float4 wv = *(const float4*)(w + r*HD + e4);
            Bt[(e4+0)*64 + swz(e4+0, r)] = wv.x;
            Bt[(e4+1)*64 + swz(e4+1, r)] = wv.y;
            Bt[(e4+2)*64 + swz(e4+2, r)] = wv.z;
            Bt[(e4+3)*64 + swz(e4+3, r)] = wv.w;
        }
        __syncthreads();
        float c[4][4] = {};
        #pragma unroll 8
        for (int e = 0; e < 64; ++e) {
            float4 a4 = *(const float4*)&At[e*64 + swz(e, ty*4)];
            float4 b4 = *(const float4*)&Bt[e*64 + swz(e, tx*4)];
            float a[4] = {a4.x, a4.y, a4.z, a4.w};
            #pragma unroll
            for (int i = 0; i < 4; ++i) {
                c[i][0] = fmaf(a[i], b4.x, c[i][0]);
                c[i][1] = fmaf(a[i], b4.y, c[i][1]);
                c[i][2] = fmaf(a[i], b4.z, c[i][2]);
                c[i][3] = fmaf(a[i], b4.w, c[i][3]);
            }
        }
        float* o = dst[t] + ((size_t)(n*HEADS + h)*LSEQ + l0)*HD;
        #pragma unroll
        for (int i = 0; i < 4; ++i) {
            float4 ov = make_float4(tf32r(c[i][0]), tf32r(c[i][1]),
                                    tf32r(c[i][2]), tf32r(c[i][3]));
            *(float4*)(o + (ty*4+i)*HD + tx*4) = ov;
        }
    }
}

// ---------------------------------------------------------------------------
// Kernel 2: pack mask bits
// ---------------------------------------------------------------------------
__global__ __launch_bounds__(256) void maskpack_kernel(const int* __restrict__ mask)
{
    const int row  = blockIdx.x;
    const int tid  = threadIdx.x;
    const int warp = tid >> 5, lane = tid & 31;
    const int* mrow = mask + (size_t)row * LSEQ;
    #pragma unroll
    for (int it = 0; it < 8; ++it) {
        int k = it*256 + warp*32 + lane;
        unsigned b = __ballot_sync(0xffffffffu, mrow[k] != 0);
        if (lane == 0) g_mb[(size_t)row*64 + it*8 + warp] = b;
    }
}

// ---------------------------------------------------------------------------
// Kernel 2b: pre-round Wo to tf32 (enables cp.async in outproj)
// ---------------------------------------------------------------------------
__global__ __launch_bounds__(256) void wo_round_kernel(const float* __restrict__ Wo)
{
    const int i = (blockIdx.x * 256 + threadIdx.x) * 4;
    float4 v = *(const float4*)(Wo + i);
    *(float4*)(g_wo + i) = make_float4(tf32r(v.x), tf32r(v.y), tf32r(v.z), tf32r(v.w));
}

// ---------------------------------------------------------------------------
// Kernel 3: tensor-core flash attention with double-buffered cp.async K/V.
// 256 thr = 8 warps; Q tile 128 rows, K tile 64 keys.
// smK stride 68 / smV stride 72 -> conflict-free B-frag LDS.
// Dynamic smem: 2 x (64*68 + 64*72) floats = 71680 B.
// ---------------------------------------------------------------------------
#define KSTR 68
#define VSTR 72
#define ABUF 8960      // floats per buffer (K 4352 + V 4608)

__global__ __launch_bounds__(256) void attn_mma_kernel()
{
    extern __shared__ float dsm[];

    const int q0   = blockIdx.x * 128;
    const int h    = blockIdx.y;
    const int n    = blockIdx.z;
    const int tid  = threadIdx.x;
    const int w    = tid >> 5;
    const int lane = tid & 31;
    const int g    = lane >> 2;
    const int t    = lane & 3;

    const size_t base = (size_t)(n*HEADS + h) * (LSEQ*HD);
    const float* Q = g_qp + base;
    const float* K = g_kp + base;
    const float* V = g_vp + base;

    // ---- Q fragments: plain loads (already tf32-rounded by proj)
    uint32_t Qa[8][4];
    {
        const uint32_t* Qr = (const uint32_t*)(Q + (size_t)(q0 + 16*w)*HD);
        #pragma unroll
        for (int s = 0; s < 8; ++s) {
            Qa[s][0] = Qr[g*HD     + 8*s + t];
            Qa[s][1] = Qr[(g+8)*HD + 8*s + t];
            Qa[s][2] = Qr[g*HD     + 8*s + t + 4];
            Qa[s][3] = Qr[(g+8)*HD + 8*s + t + 4];
        }
    }

    float O[8][4];
    #pragma unroll
    for (int j = 0; j < 8; ++j) { O[j][0]=0.f; O[j][1]=0.f; O[j][2]=0.f; O[j][3]=0.f; }
    float lsum_lo = 0.f, lsum_hi = 0.f;

    const int r0 = q0 + 16*w + g;
    const unsigned* mb0 = g_mb + (size_t)(n*LSEQ + r0) * 64;
    const unsigned* mb1 = mb0 + (size_t)8 * 64;

    const int srcA = (lane & 28) | (t >> 1);
    const int srcB = srcA + 2;
    const bool sel = (t & 1);

    auto prefetch = [&](int kt, int b) {
        const float* Kp = K + (size_t)kt*64*HD;
        const float* Vp = V + (size_t)kt*64*HD;
        uint32_t sK = smem_u32(dsm + b*ABUF);
        uint32_t sV = sK + 4352*4;
        #pragma unroll
        for (int i = tid; i < 1024; i += 256) {
            int r = i >> 4, c = (i & 15) << 2;
            cpasync16(sK + (unsigned)(r*KSTR + c)*4, Kp + (size_t)r*HD + c);
            cpasync16(sV + (unsigned)(r*VSTR + c)*4, Vp + (size_t)r*HD + c);
        }
    };

    prefetch(0, 0);
    CP_COMMIT();

    for (int kt = 0; kt < 32; ++kt) {
        const int b = kt & 1;
        __syncthreads();                 // everyone done with buffer b^1
        prefetch((kt + 1) & 31, b ^ 1);  // wraps to harmless reload at kt=31
        CP_COMMIT();
        CP_WAIT1();                      // tile kt has landed
        __syncthreads();

        const uint32_t* smKu = (const uint32_t*)(dsm + b*ABUF);
        const uint32_t* smVu = smKu + 4352;

        // ---- S = Q K^T
        float S[8][4];
        #pragma unroll
        for (int j = 0; j < 8; ++j) {
            S[j][0]=0.f; S[j][1]=0.f; S[j][2]=0.f; S[j][3]=0.f;
            const int kb = (8*j + g) * KSTR + t;
            #pragma unroll
            for (int s = 0; s < 8; ++s)
                mma8(S[j], Qa[s], smKu[kb + 8*s], smKu[kb + 8*s + 4]);
        }

        // ---- mask + exp, and P remap C-frag -> A-frag via shuffles
        const unsigned w0a = mb0[kt*2], w0b = mb0[kt*2 + 1];
        const unsigned w1a = mb1[kt*2], w1b = mb1[kt*2 + 1];
        uint32_t Pa[8][4];
        #pragma unroll
        for (int j = 0; j < 8; ++j) {
            const int cc = (8*j + 2*t) & 31;
            const unsigned wlo = (j < 4) ? w0a : w0b;
            const unsigned whi = (j < 4) ? w1a : w1b;
            float e0 = ((wlo >> cc)     & 1u) ? tf32r(__expf(S[j][0]*0.125f)) : 0.f;
            float e1 = ((wlo >> (cc+1)) & 1u) ? tf32r(__expf(S[j][1]*0.125f)) : 0.f;
            float e2 = ((whi >> cc)     & 1u) ? tf32r(__expf(S[j][2]*0.125f)) : 0.f;
            float e3 = ((whi >> (cc+1)) & 1u) ? tf32r(__expf(S[j][3]*0.125f)) : 0.f;
            lsum_lo += e0 + e1;
            lsum_hi += e2 + e3;
            float x0 = __shfl_sync(0xffffffffu, e0, srcA);
            float x1 = __shfl_sync(0xffffffffu, e1, srcA);
            Pa[j][0] = __float_as_uint(sel ? x1 : x0);
            float y0 = __shfl_sync(0xffffffffu, e2, srcA);
            float y1 = __shfl_sync(0xffffffffu, e3, srcA);
            Pa[j][1] = __float_as_uint(sel ? y1 : y0);
            x0 = __shfl_sync(0xffffffffu, e0, srcB);
            x1 = __shfl_sync(0xffffffffu, e1, srcB);
            Pa[j][2] = __float_as_uint(sel ? x1 : x0);
            y0 = __shfl_sync(0xffffffffu, e2, srcB);
            y1 = __shfl_sync(0xffffffffu, e3, srcB);
            Pa[j][3] = __float_as_uint(sel ? y1 : y0);
        }

        // ---- O += P @ V
        #pragma unroll
        for (int j = 0; j < 8; ++j) {
            const int vb = 8*j + g + t*VSTR;
            #pragma unroll
            for (int s = 0; s < 8; ++s)
                mma8(O[j], Pa[s], smVu[vb + 8*s*VSTR], smVu[vb + (8*s+4)*VSTR]);
        }
    }

    // ---- normalize + write (tf32-rounded so outproj can cp.async it raw)
    lsum_lo += __shfl_xor_sync(0xffffffffu, lsum_lo, 1);
    lsum_lo += __shfl_xor_sync(0xffffffffu, lsum_lo, 2);
    lsum_hi += __shfl_xor_sync(0xffffffffu, lsum_hi, 1);
    lsum_hi += __shfl_xor_sync(0xffffffffu, lsum_hi, 2);
    const float il = 1.f / lsum_lo;
    const float ih = 1.f / lsum_hi;

    float* o0 = g_att + (size_t)(n*LSEQ + r0)*EMB + h*HD;
    float* o1 = o0 + (size_t)8*EMB;
    #pragma unroll
    for (int j = 0; j < 8; ++j) {
        int c = 8*j + 2*t;
        *(float2*)&o0[c] = make_float2(tf32r(O[j][0]*il), tf32r(O[j][1]*il));
        *(float2*)&o1[c] = make_float2(tf32r(O[j][2]*ih), tf32r(O[j][3]*ih));
    }
}

// ---------------------------------------------------------------------------
// Kernel 4: out = att @ Wo^T + bo.  128x128 tile / block, K-chunk 32,
// double-buffered cp.async from pre-rounded g_att / g_wo.
// Dynamic smem: 2 x (128*36 + 128*36) floats = 73728 B.
// ---------------------------------------------------------------------------
#define PSTR 36
#define PBUF 9216      // floats per buffer (A 4608 + W 4608)

__global__ __launch_bounds__(256) void outproj_mma_kernel(
    const float* __restrict__ bo, float* __restrict__ out)
{
    extern __shared__ float dsm[];

    const int o0   = blockIdx.x * 128;
    const int r0b  = blockIdx.y * 128;
    const int tid  = threadIdx.x;
    const int w    = tid >> 5;
    const int lane = tid & 31;
    const int wm   = w >> 1;        // 0..3  (32-row slice)
    const int wn   = w & 1;         // 0..1  (64-col slice)
    const int g    = lane >> 2;
    const int t    = lane & 3;

    auto prefetch = [&](int ch, int b) {
        uint32_t sA = smem_u32(dsm + b*PBUF);
        uint32_t sW = sA + 4608*4;
        #pragma unroll
        for (int i = tid; i < 1024; i += 256) {
            int r = i >> 3, c = (i & 7) << 2;
            cpasync16(sA + (unsigned)(r*PSTR + c)*4,
                      g_att + (size_t)(r0b + r)*EMB + ch*32 + c);
            cpasync16(sW + (unsigned)(r*PSTR + c)*4,
                      g_wo + (size_t)(o0 + r)*EMB + ch*32 + c);
        }
    };

    float C[2][8][4];
    #pragma unroll
    for (int m = 0; m < 2; ++m)
        #pragma unroll
        for (int j = 0; j < 8; ++j) { C[m][j][0]=0.f; C[m][j][1]=0.f; C[m][j][2]=0.f; C[m][j][3]=0.f; }

    prefetch(0, 0);
    CP_COMMIT();

    for (int ch = 0; ch < 32; ++ch) {
        const int b = ch & 1;
        __syncthreads();
        prefetch((ch + 1) & 31, b ^ 1);
        CP_COMMIT();
        CP_WAIT1();
        __syncthreads();

        const uint32_t* smAu = (const uint32_t*)(dsm + b*PBUF);
        const uint32_t* smWu = smAu + 4608;

        const int ab0 = (32*wm      + g) * PSTR + t;
        const int ab1 = (32*wm + 16 + g) * PSTR + t;
        #pragma unroll
        for (int s = 0; s < 4; ++s) {
            uint32_t Aa0[4], Aa1[4];
            Aa0[0] = smAu[ab0 + 8*s];
            Aa0[1] = smAu[ab0 + 8*PSTR + 8*s];
            Aa0[2] = smAu[ab0 + 8*s + 4];
            Aa0[3] = smAu[ab0 + 8*PSTR + 8*s + 4];
            Aa1[0] = smAu[ab1 + 8*s];
            Aa1[1] = smAu[ab1 + 8*PSTR + 8*s];
            Aa1[2] = smAu[ab1 + 8*s + 4];
            Aa1[3] = smAu[ab1 + 8*PSTR + 8*s + 4];
            #pragma unroll
            for (int j = 0; j < 8; ++j) {
                const int wb = (64*wn + 8*j + g) * PSTR + t;
                uint32_t b0 = smWu[wb + 8*s], b1 = smWu[wb + 8*s + 4];
                mma8(C[0][j], Aa0, b0, b1);
                mma8(C[1][j], Aa1, b0, b1);
            }
        }
    }

    #pragma unroll
    for (int m = 0; m < 2; ++m) {
        const int row0 = r0b + 32*wm + 16*m + g;
        #pragma unroll
        for (int j = 0; j < 8; ++j) {
            int col = o0 + 64*wn + 8*j + 2*t;
            float2 bb = *(const float2*)&bo[col];
            *(float2*)&out[(size_t)row0*EMB + col] =
                make_float2(C[m][j][0] + bb.x, C[m][j][1] + bb.y);
            *(float2*)&out[(size_t)(row0+8)*EMB + col] =
                make_float2(C[m][j][2] + bb.x, C[m][j][3] + bb.y);
        }
    }
}

// ---------------------------------------------------------------------------
extern "C" void kernel_launch(void* const* d_in, const int* in_sizes, int n_in,
                              void* d_out, int out_size)
{
    (void)in_sizes; (void)n_in; (void)out_size;
    const float* vals = (const float*)d_in[0];
    const float* keys = (const float*)d_in[1];
    const float* quer = (const float*)d_in[2];
    const int*   mask = (const int*)  d_in[3];
    const float* Wv   = (const float*)d_in[4];
    const float* Wk   = (const float*)d_in[5];
    const float* Wq   = (const float*)d_in[6];
    const float* Wo   = (const float*)d_in[7];
    const float* bo   = (const float*)d_in[8];
    float* out = (float*)d_out;

    cudaFuncSetAttribute(attn_mma_kernel,
                         cudaFuncAttributeMaxDynamicSharedMemorySize, 2*ABUF*4);
    cudaFuncSetAttribute(outproj_mma_kernel,
                         cudaFuncAttributeMaxDynamicSharedMemorySize, 2*PBUF*4);

    proj_kernel      <<<dim3(LSEQ/64, HEADS, NB), 256>>>(vals, keys, quer, Wv, Wk, Wq);
    maskpack_kernel  <<<NB*LSEQ, 256>>>(mask);
    wo_round_kernel  <<<EMB*EMB/1024, 256>>>(Wo);
    attn_mma_kernel  <<<dim3(LSEQ/128, HEADS, NB), 256, 2*ABUF*4>>>();
    outproj_mma_kernel<<<dim3(EMB/128, NB*LSEQ/128), 256, 2*PBUF*4>>>(bo, out);
}